// round 1
// baseline (speedup 1.0000x reference)
#include <cuda_runtime.h>
#include <cuda_bf16.h>
#include <cstdint>

// Problem constants
#define BB 8
#define TT 1024
#define DD 1024
#define HH 16
#define KVH 8
#define HDIM 64
#define NTOK (BB*TT)          // 8192
#define QKV_N (DD + 2*KVH*HDIM) // 2048
#define FF_N (4*DD)           // 4096

// ---------------- scratch (allocation-free: __device__ globals) ----------------
__device__ float g_ln1 [NTOK * DD];     // 32 MB
__device__ float g_qkv [NTOK * QKV_N];  // 64 MB
__device__ float g_attn[NTOK * DD];     // 32 MB
__device__ float g_h   [NTOK * DD];     // 32 MB
__device__ float g_ln2 [NTOK * DD];     // 32 MB
__device__ float g_ff  [NTOK * FF_N];   // 128 MB

// ---------------- LayerNorm: one 256-thread block per row of 1024 ----------------
__global__ void ln_kernel(const float* __restrict__ x, const float* __restrict__ g,
                          const float* __restrict__ b, float* __restrict__ y) {
    __shared__ float red[16];
    const int row = blockIdx.x;
    const int tid = threadIdx.x;
    const float4* xr = (const float4*)(x + (size_t)row * DD);
    float4 v = xr[tid];
    float s  = v.x + v.y + v.z + v.w;
    float s2 = v.x*v.x + v.y*v.y + v.z*v.z + v.w*v.w;
    #pragma unroll
    for (int o = 16; o; o >>= 1) {
        s  += __shfl_xor_sync(0xffffffffu, s,  o);
        s2 += __shfl_xor_sync(0xffffffffu, s2, o);
    }
    const int wid = tid >> 5, lane = tid & 31;
    if (lane == 0) { red[wid] = s; red[wid + 8] = s2; }
    __syncthreads();
    float ts = 0.f, ts2 = 0.f;
    #pragma unroll
    for (int i = 0; i < 8; i++) { ts += red[i]; ts2 += red[i + 8]; }
    const float mu  = ts * (1.0f / DD);
    const float var = ts2 * (1.0f / DD) - mu * mu;
    const float rstd = rsqrtf(var + 1e-5f);
    float4 gv = ((const float4*)g)[tid];
    float4 bv = ((const float4*)b)[tid];
    float4 o;
    o.x = (v.x - mu) * rstd * gv.x + bv.x;
    o.y = (v.y - mu) * rstd * gv.y + bv.y;
    o.z = (v.z - mu) * rstd * gv.z + bv.z;
    o.w = (v.w - mu) * rstd * gv.w + bv.w;
    ((float4*)(y + (size_t)row * DD))[tid] = o;
}

// ---------------- GEMM: C[M,N] = A[M,K] @ B[K,N] + bias (+res) (ReLU opt) ----------------
// 128x128 tile, Ktile=16, 256 threads, 8x8 per thread.
template<bool RELU, bool RES>
__global__ void __launch_bounds__(256, 2)
gemm_kernel(const float* __restrict__ A, const float* __restrict__ B,
            const float* __restrict__ bias, const float* __restrict__ res,
            float* __restrict__ C, int M, int N, int K) {
    __shared__ float As[16][128];
    __shared__ float Bs[16][128];
    const int tid = threadIdx.x;
    const int bm = blockIdx.y * 128;
    const int bn = blockIdx.x * 128;

    const int tm = (tid / 16) * 8;
    const int tn = (tid % 16) * 8;

    const int ar = tid / 4;           // 0..63 (+64 on 2nd)
    const int ac = (tid % 4) * 4;     // 0,4,8,12
    const int br = tid / 32;          // 0..7 (+8 on 2nd)
    const int bc = (tid % 32) * 4;    // 0..124

    float c[8][8];
    #pragma unroll
    for (int i = 0; i < 8; i++)
        #pragma unroll
        for (int j = 0; j < 8; j++) c[i][j] = 0.f;

    for (int k0 = 0; k0 < K; k0 += 16) {
        #pragma unroll
        for (int i = 0; i < 2; i++) {
            float4 va = *(const float4*)(A + (size_t)(bm + ar + i * 64) * K + (k0 + ac));
            As[ac + 0][ar + i * 64] = va.x;
            As[ac + 1][ar + i * 64] = va.y;
            As[ac + 2][ar + i * 64] = va.z;
            As[ac + 3][ar + i * 64] = va.w;
        }
        #pragma unroll
        for (int i = 0; i < 2; i++) {
            float4 vb = *(const float4*)(B + (size_t)(k0 + br + i * 8) * N + (bn + bc));
            *(float4*)&Bs[br + i * 8][bc] = vb;
        }
        __syncthreads();
        #pragma unroll
        for (int kk = 0; kk < 16; kk++) {
            float a[8], bfr[8];
            #pragma unroll
            for (int i = 0; i < 8; i++) a[i] = As[kk][tm + i];
            #pragma unroll
            for (int j = 0; j < 8; j++) bfr[j] = Bs[kk][tn + j];
            #pragma unroll
            for (int i = 0; i < 8; i++)
                #pragma unroll
                for (int j = 0; j < 8; j++)
                    c[i][j] = fmaf(a[i], bfr[j], c[i][j]);
        }
        __syncthreads();
    }

    #pragma unroll
    for (int i = 0; i < 8; i++) {
        const size_t row = (size_t)(bm + tm + i);
        #pragma unroll
        for (int j = 0; j < 8; j += 4) {
            const int col = bn + tn + j;
            float4 bi = *(const float4*)(bias + col);
            float4 o;
            o.x = c[i][j + 0] + bi.x;
            o.y = c[i][j + 1] + bi.y;
            o.z = c[i][j + 2] + bi.z;
            o.w = c[i][j + 3] + bi.w;
            if (RES) {
                float4 rv = *(const float4*)(res + row * N + col);
                o.x += rv.x; o.y += rv.y; o.z += rv.z; o.w += rv.w;
            }
            if (RELU) {
                o.x = fmaxf(o.x, 0.f); o.y = fmaxf(o.y, 0.f);
                o.z = fmaxf(o.z, 0.f); o.w = fmaxf(o.w, 0.f);
            }
            *(float4*)(C + row * N + col) = o;
        }
    }
}

// ---------------- Attention: warp per (b,h,t) query row ----------------
// Effective GQA from jnp.repeat (element-wise):
//   k_eff[h][j] = kraw[h*32 + j],  q_eff[j] = q[2j] + q[2j+1],  out dims duplicated in pairs.
__global__ void attn_kernel(const float* __restrict__ qkv, float* __restrict__ out) {
    const int w = blockIdx.x * 8 + (threadIdx.x >> 5);
    const int lane = threadIdx.x & 31;
    const int t = w & (TT - 1);
    const int h = (w >> 10) & (HH - 1);
    const int b = w >> 14;

    const float* qrow = qkv + ((size_t)(b * TT + t)) * QKV_N + h * HDIM;
    const float qe = qrow[2 * lane] + qrow[2 * lane + 1];

    const float* kbase = qkv + (size_t)b * TT * QKV_N + DD + h * 32 + lane;
    const float* vbase = kbase + KVH * HDIM; // +512

    float m = -1e30f, l = 0.f, acc = 0.f;
    #pragma unroll 2
    for (int kt = 0; kt <= t; kt++) {
        float kv = kbase[(size_t)kt * QKV_N];
        float vv = vbase[(size_t)kt * QKV_N];
        float s = qe * kv;
        #pragma unroll
        for (int o = 16; o; o >>= 1) s += __shfl_xor_sync(0xffffffffu, s, o);
        s *= 0.125f; // 1/sqrt(64)
        const float mn = fmaxf(m, s);
        const float alpha = __expf(m - mn);
        const float p = __expf(s - mn);
        l = l * alpha + p;
        acc = acc * alpha + p * vv;
        m = mn;
    }
    const float o = acc / l;
    float* op = out + ((size_t)(b * TT + t)) * DD + h * HDIM + 2 * lane;
    op[0] = o;
    op[1] = o;
}

// ---------------- launch ----------------
extern "C" void kernel_launch(void* const* d_in, const int* in_sizes, int n_in,
                              void* d_out, int out_size) {
    const float* x     = (const float*)d_in[0];
    const float* ln1_g = (const float*)d_in[1];
    const float* ln1_b = (const float*)d_in[2];
    const float* Wqkv  = (const float*)d_in[3];
    const float* bqkv  = (const float*)d_in[4];
    const float* Wo    = (const float*)d_in[5];
    const float* bo    = (const float*)d_in[6];
    const float* ln2_g = (const float*)d_in[7];
    const float* ln2_b = (const float*)d_in[8];
    const float* W1    = (const float*)d_in[9];
    const float* b1    = (const float*)d_in[10];
    const float* W2    = (const float*)d_in[11];
    const float* b2    = (const float*)d_in[12];
    float* out = (float*)d_out;

    float *p_ln1, *p_qkv, *p_attn, *p_h, *p_ln2, *p_ff;
    cudaGetSymbolAddress((void**)&p_ln1,  g_ln1);
    cudaGetSymbolAddress((void**)&p_qkv,  g_qkv);
    cudaGetSymbolAddress((void**)&p_attn, g_attn);
    cudaGetSymbolAddress((void**)&p_h,    g_h);
    cudaGetSymbolAddress((void**)&p_ln2,  g_ln2);
    cudaGetSymbolAddress((void**)&p_ff,   g_ff);

    // 1) LN1
    ln_kernel<<<NTOK, 256>>>(x, ln1_g, ln1_b, p_ln1);
    // 2) QKV GEMM: [8192,1024] x [1024,2048]
    gemm_kernel<false, false><<<dim3(QKV_N / 128, NTOK / 128), 256>>>(
        p_ln1, Wqkv, bqkv, nullptr, p_qkv, NTOK, QKV_N, DD);
    // 3) Attention
    attn_kernel<<<(BB * HH * TT) / 8, 256>>>(p_qkv, p_attn);
    // 4) Wo GEMM + residual x -> h
    gemm_kernel<false, true><<<dim3(DD / 128, NTOK / 128), 256>>>(
        p_attn, Wo, bo, x, p_h, NTOK, DD, DD);
    // 5) LN2
    ln_kernel<<<NTOK, 256>>>(p_h, ln2_g, ln2_b, p_ln2);
    // 6) W1 GEMM + ReLU
    gemm_kernel<true, false><<<dim3(FF_N / 128, NTOK / 128), 256>>>(
        p_ln2, W1, b1, nullptr, p_ff, NTOK, FF_N, DD);
    // 7) W2 GEMM + bias + residual x -> out
    gemm_kernel<false, true><<<dim3(DD / 128, NTOK / 128), 256>>>(
        p_ff, W2, b2, x, out, NTOK, DD, FF_N);
}

// round 2
// speedup vs baseline: 2.3130x; 2.3130x over previous
#include <cuda_runtime.h>
#include <cuda_bf16.h>
#include <cstdint>

// Problem constants
#define BB 8
#define TT 1024
#define DD 1024
#define HH 16
#define KVH 8
#define HDIM 64
#define NTOK (BB*TT)            // 8192
#define QKV_N (DD + 2*KVH*HDIM) // 2048
#define FF_N (4*DD)             // 4096

// ---------------- scratch (allocation-free: __device__ globals) ----------------
__device__ float g_ln1 [NTOK * DD];
__device__ float g_qkv [NTOK * QKV_N];
__device__ float g_attn[NTOK * DD];
__device__ float g_h   [NTOK * DD];
__device__ float g_ln2 [NTOK * DD];
__device__ float g_ff  [NTOK * FF_N];

// ---------------- LayerNorm ----------------
__global__ void ln_kernel(const float* __restrict__ x, const float* __restrict__ g,
                          const float* __restrict__ b, float* __restrict__ y) {
    __shared__ float red[16];
    const int row = blockIdx.x;
    const int tid = threadIdx.x;
    const float4* xr = (const float4*)(x + (size_t)row * DD);
    float4 v = xr[tid];
    float s  = v.x + v.y + v.z + v.w;
    float s2 = v.x*v.x + v.y*v.y + v.z*v.z + v.w*v.w;
    #pragma unroll
    for (int o = 16; o; o >>= 1) {
        s  += __shfl_xor_sync(0xffffffffu, s,  o);
        s2 += __shfl_xor_sync(0xffffffffu, s2, o);
    }
    const int wid = tid >> 5, lane = tid & 31;
    if (lane == 0) { red[wid] = s; red[wid + 8] = s2; }
    __syncthreads();
    float ts = 0.f, ts2 = 0.f;
    #pragma unroll
    for (int i = 0; i < 8; i++) { ts += red[i]; ts2 += red[i + 8]; }
    const float mu  = ts * (1.0f / DD);
    const float var = ts2 * (1.0f / DD) - mu * mu;
    const float rstd = rsqrtf(var + 1e-5f);
    float4 gv = ((const float4*)g)[tid];
    float4 bv = ((const float4*)b)[tid];
    float4 o;
    o.x = (v.x - mu) * rstd * gv.x + bv.x;
    o.y = (v.y - mu) * rstd * gv.y + bv.y;
    o.z = (v.z - mu) * rstd * gv.z + bv.z;
    o.w = (v.w - mu) * rstd * gv.w + bv.w;
    ((float4*)(y + (size_t)row * DD))[tid] = o;
}

// ---------------- tf32 helpers ----------------
__device__ __forceinline__ uint32_t f2tf(float f) {
    uint32_t r;
    asm("cvt.rna.tf32.f32 %0, %1;" : "=r"(r) : "f"(f));
    return r;
}
__device__ __forceinline__ void mma_tf32(float& d0, float& d1, float& d2, float& d3,
                                         uint32_t a0, uint32_t a1, uint32_t a2, uint32_t a3,
                                         uint32_t b0, uint32_t b1) {
    asm volatile(
        "mma.sync.aligned.m16n8k8.row.col.f32.tf32.tf32.f32 "
        "{%0,%1,%2,%3}, {%4,%5,%6,%7}, {%8,%9}, {%0,%1,%2,%3};\n"
        : "+f"(d0), "+f"(d1), "+f"(d2), "+f"(d3)
        : "r"(a0), "r"(a1), "r"(a2), "r"(a3), "r"(b0), "r"(b1));
}

// ---------------- GEMM: C = A[M,K] @ B[K,N] + bias (+res)(ReLU) via tf32 mma ----------------
// 128x128 block tile, Ktile=16 double-buffered, 8 warps each 64x32.
template<bool RELU, bool RES>
__global__ void __launch_bounds__(256)
gemm_tc(const float* __restrict__ A, const float* __restrict__ B,
        const float* __restrict__ bias, const float* __restrict__ res,
        float* __restrict__ C, int M, int N, int K) {
    __shared__ float As[2][16][132];
    __shared__ float Bs[2][16][132];

    const int tid  = threadIdx.x;
    const int lane = tid & 31;
    const int wid  = tid >> 5;
    const int gid  = lane >> 2;   // 0..7
    const int tig  = lane & 3;    // 0..3
    const int warpM = (wid & 1) * 64;
    const int warpN = (wid >> 1) * 32;

    const int bm = blockIdx.y * 128;
    const int bn = blockIdx.x * 128;

    // global->reg staging indices
    const int ar = tid >> 2;          // 0..63 (+64)
    const int ac = (tid & 3) * 4;     // 0,4,8,12
    const int br = tid >> 5;          // 0..7 (+8)
    const int bc = (tid & 31) * 4;    // 0..124

    float c[4][4][4];
    #pragma unroll
    for (int i = 0; i < 4; i++)
        #pragma unroll
        for (int j = 0; j < 4; j++)
            #pragma unroll
            for (int q = 0; q < 4; q++) c[i][j][q] = 0.f;

    float4 ra[2], rb[2];
    // preload tile 0
    #pragma unroll
    for (int i = 0; i < 2; i++) {
        ra[i] = *(const float4*)(A + (size_t)(bm + ar + i*64) * K + ac);
        rb[i] = *(const float4*)(B + (size_t)(br + i*8) * N + bn + bc);
    }
    #pragma unroll
    for (int i = 0; i < 2; i++) {
        As[0][ac+0][ar+i*64] = __uint_as_float(f2tf(ra[i].x));
        As[0][ac+1][ar+i*64] = __uint_as_float(f2tf(ra[i].y));
        As[0][ac+2][ar+i*64] = __uint_as_float(f2tf(ra[i].z));
        As[0][ac+3][ar+i*64] = __uint_as_float(f2tf(ra[i].w));
        float4 t;
        t.x = __uint_as_float(f2tf(rb[i].x));
        t.y = __uint_as_float(f2tf(rb[i].y));
        t.z = __uint_as_float(f2tf(rb[i].z));
        t.w = __uint_as_float(f2tf(rb[i].w));
        *(float4*)&Bs[0][br+i*8][bc] = t;
    }
    __syncthreads();

    const int nT = K / 16;
    int cur = 0;
    for (int t = 0; t < nT; t++) {
        if (t + 1 < nT) {
            const int k0 = (t + 1) * 16;
            #pragma unroll
            for (int i = 0; i < 2; i++) {
                ra[i] = *(const float4*)(A + (size_t)(bm + ar + i*64) * K + k0 + ac);
                rb[i] = *(const float4*)(B + (size_t)(k0 + br + i*8) * N + bn + bc);
            }
        }
        // compute on smem[cur]
        #pragma unroll
        for (int kk = 0; kk < 16; kk += 8) {
            uint32_t af[4][4], bf[4][2];
            #pragma unroll
            for (int mi = 0; mi < 4; mi++) {
                const int m0 = warpM + mi*16 + gid;
                af[mi][0] = __float_as_uint(As[cur][kk+tig  ][m0]);
                af[mi][1] = __float_as_uint(As[cur][kk+tig  ][m0+8]);
                af[mi][2] = __float_as_uint(As[cur][kk+tig+4][m0]);
                af[mi][3] = __float_as_uint(As[cur][kk+tig+4][m0+8]);
            }
            #pragma unroll
            for (int ni = 0; ni < 4; ni++) {
                const int n0 = warpN + ni*8 + gid;
                bf[ni][0] = __float_as_uint(Bs[cur][kk+tig  ][n0]);
                bf[ni][1] = __float_as_uint(Bs[cur][kk+tig+4][n0]);
            }
            #pragma unroll
            for (int mi = 0; mi < 4; mi++)
                #pragma unroll
                for (int ni = 0; ni < 4; ni++)
                    mma_tf32(c[mi][ni][0], c[mi][ni][1], c[mi][ni][2], c[mi][ni][3],
                             af[mi][0], af[mi][1], af[mi][2], af[mi][3],
                             bf[ni][0], bf[ni][1]);
        }
        if (t + 1 < nT) {
            __syncthreads();
            const int nxt = cur ^ 1;
            #pragma unroll
            for (int i = 0; i < 2; i++) {
                As[nxt][ac+0][ar+i*64] = __uint_as_float(f2tf(ra[i].x));
                As[nxt][ac+1][ar+i*64] = __uint_as_float(f2tf(ra[i].y));
                As[nxt][ac+2][ar+i*64] = __uint_as_float(f2tf(ra[i].z));
                As[nxt][ac+3][ar+i*64] = __uint_as_float(f2tf(ra[i].w));
                float4 tb;
                tb.x = __uint_as_float(f2tf(rb[i].x));
                tb.y = __uint_as_float(f2tf(rb[i].y));
                tb.z = __uint_as_float(f2tf(rb[i].z));
                tb.w = __uint_as_float(f2tf(rb[i].w));
                *(float4*)&Bs[nxt][br+i*8][bc] = tb;
            }
            __syncthreads();
            cur = nxt;
        }
    }

    // epilogue
    #pragma unroll
    for (int mi = 0; mi < 4; mi++) {
        #pragma unroll
        for (int ni = 0; ni < 4; ni++) {
            const int col = bn + warpN + ni*8 + 2*tig;
            const size_t r0 = (size_t)(bm + warpM + mi*16 + gid);
            const size_t r1 = r0 + 8;
            float2 bi = *(const float2*)(bias + col);
            float2 o0, o1;
            o0.x = c[mi][ni][0] + bi.x; o0.y = c[mi][ni][1] + bi.y;
            o1.x = c[mi][ni][2] + bi.x; o1.y = c[mi][ni][3] + bi.y;
            if (RES) {
                float2 v0 = *(const float2*)(res + r0 * N + col);
                float2 v1 = *(const float2*)(res + r1 * N + col);
                o0.x += v0.x; o0.y += v0.y; o1.x += v1.x; o1.y += v1.y;
            }
            if (RELU) {
                o0.x = fmaxf(o0.x, 0.f); o0.y = fmaxf(o0.y, 0.f);
                o1.x = fmaxf(o1.x, 0.f); o1.y = fmaxf(o1.y, 0.f);
            }
            *(float2*)(C + r0 * N + col) = o0;
            *(float2*)(C + r1 * N + col) = o1;
        }
    }
}

// ---------------- Attention ----------------
// Effective GQA (elementwise jnp.repeat): head h uses 32-dim slices
//   k_eff[j]=kraw[h*32+j], q_eff[j]=q[h*64+2j]+q[h*64+2j+1], out duplicated in pairs.
// Block: 64 queries of one (b,h); key tiles of 32 in smem; 8 warps x 8 queries.
__global__ void __launch_bounds__(256)
attn_kernel(const float* __restrict__ qkv, float* __restrict__ out) {
    __shared__ float q_s[64][33];
    __shared__ float k_s[32][33];
    __shared__ float v_s[32][33];

    const int tid  = threadIdx.x;
    const int lane = tid & 31;
    const int warp = tid >> 5;
    const int bh = blockIdx.y;
    const int b = bh >> 4;
    const int h = bh & 15;
    const int qt0 = blockIdx.x * 64;
    const float* base = qkv + (size_t)b * TT * QKV_N;

    // load q_eff tile: 64 x 32
    {
        const int ql = tid >> 2;
        const int d0 = (tid & 3) * 8;
        const float4* qr = (const float4*)(base + (size_t)(qt0 + ql) * QKV_N + h * HDIM + d0 * 2);
        #pragma unroll
        for (int i = 0; i < 4; i++) {
            float4 v = qr[i];
            q_s[ql][d0 + 2*i]     = v.x + v.y;
            q_s[ql][d0 + 2*i + 1] = v.z + v.w;
        }
    }

    float m[8], l[8], acc[8];
    #pragma unroll
    for (int r = 0; r < 8; r++) { m[r] = -1e30f; l[r] = 0.f; acc[r] = 0.f; }

    const int kend = qt0 + 64;
    for (int s = 0; s < kend; s += 32) {
        __syncthreads();
        {
            const int j  = tid >> 3;
            const int d0 = (tid & 7) * 4;
            const float* kr = base + (size_t)(s + j) * QKV_N + DD + h * 32 + d0;
            float4 k4 = *(const float4*)kr;
            float4 v4 = *(const float4*)(kr + KVH * HDIM);
            k_s[j][d0] = k4.x; k_s[j][d0+1] = k4.y; k_s[j][d0+2] = k4.z; k_s[j][d0+3] = k4.w;
            v_s[j][d0] = v4.x; v_s[j][d0+1] = v4.y; v_s[j][d0+2] = v4.z; v_s[j][d0+3] = v4.w;
        }
        __syncthreads();

        #pragma unroll
        for (int r = 0; r < 8; r++) {
            const int ql = r * 8 + warp;
            const int t = qt0 + ql;
            if (s > t) continue;
            // score for key (s+lane)
            float sc = 0.f;
            #pragma unroll
            for (int d = 0; d < 32; d++)
                sc = fmaf(q_s[ql][d], k_s[lane][d], sc);
            sc *= 0.125f;
            if (s + lane > t) sc = -1e30f;
            // tile max
            float mt = sc;
            #pragma unroll
            for (int o = 16; o; o >>= 1) mt = fmaxf(mt, __shfl_xor_sync(0xffffffffu, mt, o));
            const float mn = fmaxf(m[r], mt);
            const float alpha = __expf(m[r] - mn);
            const float p = __expf(sc - mn);
            float ps = p;
            #pragma unroll
            for (int o = 16; o; o >>= 1) ps += __shfl_xor_sync(0xffffffffu, ps, o);
            l[r] = l[r] * alpha + ps;
            m[r] = mn;
            acc[r] *= alpha;
            #pragma unroll
            for (int jj = 0; jj < 32; jj++) {
                const float pj = __shfl_sync(0xffffffffu, p, jj);
                acc[r] = fmaf(pj, v_s[jj][lane], acc[r]);
            }
        }
    }

    #pragma unroll
    for (int r = 0; r < 8; r++) {
        const int ql = r * 8 + warp;
        const int t = qt0 + ql;
        const float o = acc[r] / l[r];
        float2 st; st.x = o; st.y = o;
        *(float2*)(out + (size_t)((b * TT + t)) * DD + h * HDIM + 2 * lane) = st;
    }
}

// ---------------- launch ----------------
extern "C" void kernel_launch(void* const* d_in, const int* in_sizes, int n_in,
                              void* d_out, int out_size) {
    const float* x     = (const float*)d_in[0];
    const float* ln1_g = (const float*)d_in[1];
    const float* ln1_b = (const float*)d_in[2];
    const float* Wqkv  = (const float*)d_in[3];
    const float* bqkv  = (const float*)d_in[4];
    const float* Wo    = (const float*)d_in[5];
    const float* bo    = (const float*)d_in[6];
    const float* ln2_g = (const float*)d_in[7];
    const float* ln2_b = (const float*)d_in[8];
    const float* W1    = (const float*)d_in[9];
    const float* b1    = (const float*)d_in[10];
    const float* W2    = (const float*)d_in[11];
    const float* b2    = (const float*)d_in[12];
    float* out = (float*)d_out;

    float *p_ln1, *p_qkv, *p_attn, *p_h, *p_ln2, *p_ff;
    cudaGetSymbolAddress((void**)&p_ln1,  g_ln1);
    cudaGetSymbolAddress((void**)&p_qkv,  g_qkv);
    cudaGetSymbolAddress((void**)&p_attn, g_attn);
    cudaGetSymbolAddress((void**)&p_h,    g_h);
    cudaGetSymbolAddress((void**)&p_ln2,  g_ln2);
    cudaGetSymbolAddress((void**)&p_ff,   g_ff);

    ln_kernel<<<NTOK, 256>>>(x, ln1_g, ln1_b, p_ln1);
    gemm_tc<false, false><<<dim3(QKV_N / 128, NTOK / 128), 256>>>(
        p_ln1, Wqkv, bqkv, nullptr, p_qkv, NTOK, QKV_N, DD);
    attn_kernel<<<dim3(TT / 64, BB * HH), 256>>>(p_qkv, p_attn);
    gemm_tc<false, true><<<dim3(DD / 128, NTOK / 128), 256>>>(
        p_attn, Wo, bo, x, p_h, NTOK, DD, DD);
    ln_kernel<<<NTOK, 256>>>(p_h, ln2_g, ln2_b, p_ln2);
    gemm_tc<true, false><<<dim3(FF_N / 128, NTOK / 128), 256>>>(
        p_ln2, W1, b1, nullptr, p_ff, NTOK, FF_N, DD);
    gemm_tc<false, true><<<dim3(DD / 128, NTOK / 128), 256>>>(
        p_ff, W2, b2, x, out, NTOK, DD, FF_N);
}

// round 6
// speedup vs baseline: 3.2868x; 1.4210x over previous
#include <cuda_runtime.h>
#include <cuda_bf16.h>
#include <cstdint>

// Problem constants
#define BB 8
#define TT 1024
#define DD 1024
#define HH 16
#define KVH 8
#define HDIM 64
#define NTOK (BB*TT)            // 8192
#define QKV_N (DD + 2*KVH*HDIM) // 2048
#define FF_N (4*DD)             // 4096

// ---------------- scratch ----------------
__device__ float g_ln1 [NTOK * DD];
__device__ float g_qkv [NTOK * QKV_N];
__device__ float g_attn[NTOK * DD];
__device__ float g_h   [NTOK * DD];
__device__ float g_ln2 [NTOK * DD];
__device__ float g_ff  [NTOK * FF_N];

// ---------------- tf32 helpers ----------------
__device__ __forceinline__ uint32_t f2tf(float f) {
    uint32_t r;
    asm("cvt.rna.tf32.f32 %0, %1;" : "=r"(r) : "f"(f));
    return r;
}
__device__ __forceinline__ float f2tff(float f) { return __uint_as_float(f2tf(f)); }

__device__ __forceinline__ void mma_tf32(float& d0, float& d1, float& d2, float& d3,
                                         uint32_t a0, uint32_t a1, uint32_t a2, uint32_t a3,
                                         uint32_t b0, uint32_t b1) {
    asm volatile(
        "mma.sync.aligned.m16n8k8.row.col.f32.tf32.tf32.f32 "
        "{%0,%1,%2,%3}, {%4,%5,%6,%7}, {%8,%9}, {%0,%1,%2,%3};\n"
        : "+f"(d0), "+f"(d1), "+f"(d2), "+f"(d3)
        : "r"(a0), "r"(a1), "r"(a2), "r"(a3), "r"(b0), "r"(b1));
}

// ---------------- LayerNorm ----------------
__global__ void ln_kernel(const float* __restrict__ x, const float* __restrict__ g,
                          const float* __restrict__ b, float* __restrict__ y) {
    __shared__ float red[16];
    const int row = blockIdx.x;
    const int tid = threadIdx.x;
    const float4* xr = (const float4*)(x + (size_t)row * DD);
    float4 v = xr[tid];
    float s  = v.x + v.y + v.z + v.w;
    float s2 = v.x*v.x + v.y*v.y + v.z*v.z + v.w*v.w;
    #pragma unroll
    for (int o = 16; o; o >>= 1) {
        s  += __shfl_xor_sync(0xffffffffu, s,  o);
        s2 += __shfl_xor_sync(0xffffffffu, s2, o);
    }
    const int wid = tid >> 5, lane = tid & 31;
    if (lane == 0) { red[wid] = s; red[wid + 8] = s2; }
    __syncthreads();
    float ts = 0.f, ts2 = 0.f;
    #pragma unroll
    for (int i = 0; i < 8; i++) { ts += red[i]; ts2 += red[i + 8]; }
    const float mu  = ts * (1.0f / DD);
    const float var = ts2 * (1.0f / DD) - mu * mu;
    const float rstd = rsqrtf(var + 1e-5f);
    float4 gv = ((const float4*)g)[tid];
    float4 bv = ((const float4*)b)[tid];
    float4 o;
    o.x = (v.x - mu) * rstd * gv.x + bv.x;
    o.y = (v.y - mu) * rstd * gv.y + bv.y;
    o.z = (v.z - mu) * rstd * gv.z + bv.z;
    o.w = (v.w - mu) * rstd * gv.w + bv.w;
    ((float4*)(y + (size_t)row * DD))[tid] = o;
}

// ---------------- GEMM (validated tf32 mma path) ----------------
template<bool RELU, bool RES>
__global__ void __launch_bounds__(256)
gemm_tc(const float* __restrict__ A, const float* __restrict__ B,
        const float* __restrict__ bias, const float* __restrict__ res,
        float* __restrict__ C, int M, int N, int K) {
    __shared__ float As[2][16][132];
    __shared__ float Bs[2][16][132];

    const int tid  = threadIdx.x;
    const int lane = tid & 31;
    const int wid  = tid >> 5;
    const int gid  = lane >> 2;
    const int tig  = lane & 3;
    const int warpM = (wid & 1) * 64;
    const int warpN = (wid >> 1) * 32;

    const int bm = blockIdx.y * 128;
    const int bn = blockIdx.x * 128;

    const int ar = tid >> 2;
    const int ac = (tid & 3) * 4;
    const int br = tid >> 5;
    const int bc = (tid & 31) * 4;

    float c[4][4][4];
    #pragma unroll
    for (int i = 0; i < 4; i++)
        #pragma unroll
        for (int j = 0; j < 4; j++)
            #pragma unroll
            for (int q = 0; q < 4; q++) c[i][j][q] = 0.f;

    float4 ra[2], rb[2];
    #pragma unroll
    for (int i = 0; i < 2; i++) {
        ra[i] = *(const float4*)(A + (size_t)(bm + ar + i*64) * K + ac);
        rb[i] = *(const float4*)(B + (size_t)(br + i*8) * N + bn + bc);
    }
    #pragma unroll
    for (int i = 0; i < 2; i++) {
        As[0][ac+0][ar+i*64] = f2tff(ra[i].x);
        As[0][ac+1][ar+i*64] = f2tff(ra[i].y);
        As[0][ac+2][ar+i*64] = f2tff(ra[i].z);
        As[0][ac+3][ar+i*64] = f2tff(ra[i].w);
        float4 t;
        t.x = f2tff(rb[i].x); t.y = f2tff(rb[i].y);
        t.z = f2tff(rb[i].z); t.w = f2tff(rb[i].w);
        *(float4*)&Bs[0][br+i*8][bc] = t;
    }
    __syncthreads();

    const int nT = K / 16;
    int cur = 0;
    for (int t = 0; t < nT; t++) {
        if (t + 1 < nT) {
            const int k0 = (t + 1) * 16;
            #pragma unroll
            for (int i = 0; i < 2; i++) {
                ra[i] = *(const float4*)(A + (size_t)(bm + ar + i*64) * K + k0 + ac);
                rb[i] = *(const float4*)(B + (size_t)(k0 + br + i*8) * N + bn + bc);
            }
        }
        #pragma unroll
        for (int kk = 0; kk < 16; kk += 8) {
            uint32_t af[4][4], bf[4][2];
            #pragma unroll
            for (int mi = 0; mi < 4; mi++) {
                const int m0 = warpM + mi*16 + gid;
                af[mi][0] = __float_as_uint(As[cur][kk+tig  ][m0]);
                af[mi][1] = __float_as_uint(As[cur][kk+tig  ][m0+8]);
                af[mi][2] = __float_as_uint(As[cur][kk+tig+4][m0]);
                af[mi][3] = __float_as_uint(As[cur][kk+tig+4][m0+8]);
            }
            #pragma unroll
            for (int ni = 0; ni < 4; ni++) {
                const int n0 = warpN + ni*8 + gid;
                bf[ni][0] = __float_as_uint(Bs[cur][kk+tig  ][n0]);
                bf[ni][1] = __float_as_uint(Bs[cur][kk+tig+4][n0]);
            }
            #pragma unroll
            for (int mi = 0; mi < 4; mi++)
                #pragma unroll
                for (int ni = 0; ni < 4; ni++)
                    mma_tf32(c[mi][ni][0], c[mi][ni][1], c[mi][ni][2], c[mi][ni][3],
                             af[mi][0], af[mi][1], af[mi][2], af[mi][3],
                             bf[ni][0], bf[ni][1]);
        }
        if (t + 1 < nT) {
            __syncthreads();
            const int nxt = cur ^ 1;
            #pragma unroll
            for (int i = 0; i < 2; i++) {
                As[nxt][ac+0][ar+i*64] = f2tff(ra[i].x);
                As[nxt][ac+1][ar+i*64] = f2tff(ra[i].y);
                As[nxt][ac+2][ar+i*64] = f2tff(ra[i].z);
                As[nxt][ac+3][ar+i*64] = f2tff(ra[i].w);
                float4 tb;
                tb.x = f2tff(rb[i].x); tb.y = f2tff(rb[i].y);
                tb.z = f2tff(rb[i].z); tb.w = f2tff(rb[i].w);
                *(float4*)&Bs[nxt][br+i*8][bc] = tb;
            }
            __syncthreads();
            cur = nxt;
        }
    }

    #pragma unroll
    for (int mi = 0; mi < 4; mi++) {
        #pragma unroll
        for (int ni = 0; ni < 4; ni++) {
            const int col = bn + warpN + ni*8 + 2*tig;
            const size_t r0 = (size_t)(bm + warpM + mi*16 + gid);
            const size_t r1 = r0 + 8;
            float2 bi = *(const float2*)(bias + col);
            float2 o0, o1;
            o0.x = c[mi][ni][0] + bi.x; o0.y = c[mi][ni][1] + bi.y;
            o1.x = c[mi][ni][2] + bi.x; o1.y = c[mi][ni][3] + bi.y;
            if (RES) {
                float2 v0 = *(const float2*)(res + r0 * N + col);
                float2 v1 = *(const float2*)(res + r1 * N + col);
                o0.x += v0.x; o0.y += v0.y; o1.x += v1.x; o1.y += v1.y;
            }
            if (RELU) {
                o0.x = fmaxf(o0.x, 0.f); o0.y = fmaxf(o0.y, 0.f);
                o1.x = fmaxf(o1.x, 0.f); o1.y = fmaxf(o1.y, 0.f);
            }
            *(float2*)(C + r0 * N + col) = o0;
            *(float2*)(C + r1 * N + col) = o1;
        }
    }
}

// ---------------- Attention via tf32 mma ----------------
// Effective GQA (elementwise jnp.repeat): head h uses 32-dim slices
//   k_eff[j]=kraw[h*32+j], q_eff[j]=q[h*64+2j]+q[h*64+2j+1], out duplicated in pairs.
__global__ void __launch_bounds__(128)
attn_mma(const float* __restrict__ qkv, float* __restrict__ out) {
    __shared__ float q_s[64][33];
    __shared__ float k_s[32][33];
    __shared__ float v_s[32][33];
    __shared__ float p_s[64][34];

    const int tid  = threadIdx.x;
    const int lane = tid & 31;
    const int warp = tid >> 5;
    const int gid  = lane >> 2;   // 0..7
    const int tig  = lane & 3;    // 0..3
    const int b   = blockIdx.y >> 4;
    const int h   = blockIdx.y & 15;
    const int qt0 = blockIdx.x * 64;
    const float* base = qkv + (size_t)b * TT * QKV_N;

    // load q_eff tile 64x32 (tf32). Each thread covers 32 raw q elems -> 16 eff cols.
    // FIX vs R3: 8 float4 reads (was 4 -> left half of q_s uninitialized).
    {
        const int row = tid >> 1, half = tid & 1;
        const float4* qr = (const float4*)(base + (size_t)(qt0 + row) * QKV_N + h * HDIM + half * 32);
        #pragma unroll
        for (int i = 0; i < 8; i++) {
            float4 v = qr[i];
            q_s[row][half*16 + 2*i]     = f2tff(v.x + v.y);
            q_s[row][half*16 + 2*i + 1] = f2tff(v.z + v.w);
        }
    }

    const int m0 = warp * 16;
    const int r0g = qt0 + m0 + gid;
    const int r1g = r0g + 8;
    float mrow0 = -1e30f, mrow1 = -1e30f, lrow0 = 0.f, lrow1 = 0.f;
    float o[4][4];
    #pragma unroll
    for (int i = 0; i < 4; i++)
        #pragma unroll
        for (int j = 0; j < 4; j++) o[i][j] = 0.f;

    for (int s = 0; s < qt0 + 64; s += 32) {
        __syncthreads();   // covers q_s (first iter) + prior-iter reads of k_s/v_s
        {
            const int r = tid >> 2, c0 = (tid & 3) * 8;
            const float* kr = base + (size_t)(s + r) * QKV_N + DD + h * 32 + c0;
            float4 ka = *(const float4*)kr;
            float4 kb = *(const float4*)(kr + 4);
            float4 va = *(const float4*)(kr + KVH * HDIM);
            float4 vb = *(const float4*)(kr + KVH * HDIM + 4);
            k_s[r][c0+0]=f2tff(ka.x); k_s[r][c0+1]=f2tff(ka.y); k_s[r][c0+2]=f2tff(ka.z); k_s[r][c0+3]=f2tff(ka.w);
            k_s[r][c0+4]=f2tff(kb.x); k_s[r][c0+5]=f2tff(kb.y); k_s[r][c0+6]=f2tff(kb.z); k_s[r][c0+7]=f2tff(kb.w);
            v_s[r][c0+0]=f2tff(va.x); v_s[r][c0+1]=f2tff(va.y); v_s[r][c0+2]=f2tff(va.z); v_s[r][c0+3]=f2tff(va.w);
            v_s[r][c0+4]=f2tff(vb.x); v_s[r][c0+5]=f2tff(vb.y); v_s[r][c0+6]=f2tff(vb.z); v_s[r][c0+7]=f2tff(vb.w);
        }
        __syncthreads();

        // ---- S = Q K^T : 16x32 per warp ----
        float c[4][4];
        #pragma unroll
        for (int ni = 0; ni < 4; ni++)
            #pragma unroll
            for (int q = 0; q < 4; q++) c[ni][q] = 0.f;

        #pragma unroll
        for (int kk = 0; kk < 4; kk++) {
            uint32_t a0 = __float_as_uint(q_s[m0+gid  ][kk*8+tig  ]);
            uint32_t a1 = __float_as_uint(q_s[m0+gid+8][kk*8+tig  ]);
            uint32_t a2 = __float_as_uint(q_s[m0+gid  ][kk*8+tig+4]);
            uint32_t a3 = __float_as_uint(q_s[m0+gid+8][kk*8+tig+4]);
            #pragma unroll
            for (int ni = 0; ni < 4; ni++) {
                uint32_t b0 = __float_as_uint(k_s[ni*8+gid][kk*8+tig  ]);
                uint32_t b1 = __float_as_uint(k_s[ni*8+gid][kk*8+tig+4]);
                mma_tf32(c[ni][0], c[ni][1], c[ni][2], c[ni][3], a0, a1, a2, a3, b0, b1);
            }
        }

        // ---- scale + causal mask ----
        #pragma unroll
        for (int ni = 0; ni < 4; ni++) {
            const int col = s + ni*8 + 2*tig;
            c[ni][0] = (col   <= r0g) ? c[ni][0]*0.125f : -1e30f;
            c[ni][1] = (col+1 <= r0g) ? c[ni][1]*0.125f : -1e30f;
            c[ni][2] = (col   <= r1g) ? c[ni][2]*0.125f : -1e30f;
            c[ni][3] = (col+1 <= r1g) ? c[ni][3]*0.125f : -1e30f;
        }

        // ---- row max + quad reduce ----
        float mt0 = c[0][0], mt1 = c[0][2];
        #pragma unroll
        for (int ni = 0; ni < 4; ni++) {
            mt0 = fmaxf(mt0, fmaxf(c[ni][0], c[ni][1]));
            mt1 = fmaxf(mt1, fmaxf(c[ni][2], c[ni][3]));
        }
        #pragma unroll
        for (int off = 1; off <= 2; off <<= 1) {
            mt0 = fmaxf(mt0, __shfl_xor_sync(0xffffffffu, mt0, off));
            mt1 = fmaxf(mt1, __shfl_xor_sync(0xffffffffu, mt1, off));
        }
        const float mn0 = fmaxf(mrow0, mt0);
        const float mn1 = fmaxf(mrow1, mt1);
        const float al0 = __expf(mrow0 - mn0);
        const float al1 = __expf(mrow1 - mn1);
        mrow0 = mn0; mrow1 = mn1;

        // ---- p = exp(s-m), partial sums, store to p_s ----
        float ps0 = 0.f, ps1 = 0.f;
        #pragma unroll
        for (int ni = 0; ni < 4; ni++) {
            float p00 = __expf(c[ni][0] - mn0);
            float p01 = __expf(c[ni][1] - mn0);
            float p10 = __expf(c[ni][2] - mn1);
            float p11 = __expf(c[ni][3] - mn1);
            ps0 += p00 + p01; ps1 += p10 + p11;
            float2 w0; w0.x = f2tff(p00); w0.y = f2tff(p01);
            float2 w1; w1.x = f2tff(p10); w1.y = f2tff(p11);
            *(float2*)&p_s[m0+gid  ][ni*8 + 2*tig] = w0;
            *(float2*)&p_s[m0+gid+8][ni*8 + 2*tig] = w1;
        }
        #pragma unroll
        for (int off = 1; off <= 2; off <<= 1) {
            ps0 += __shfl_xor_sync(0xffffffffu, ps0, off);
            ps1 += __shfl_xor_sync(0xffffffffu, ps1, off);
        }
        lrow0 = lrow0 * al0 + ps0;
        lrow1 = lrow1 * al1 + ps1;
        #pragma unroll
        for (int ni = 0; ni < 4; ni++) {
            o[ni][0] *= al0; o[ni][1] *= al0;
            o[ni][2] *= al1; o[ni][3] *= al1;
        }
        __syncwarp();   // order p_s STS before LDS (warp-private rows)

        // ---- O += P V : 16x32 per warp ----
        #pragma unroll
        for (int kk = 0; kk < 4; kk++) {
            uint32_t a0 = __float_as_uint(p_s[m0+gid  ][kk*8+tig  ]);
            uint32_t a1 = __float_as_uint(p_s[m0+gid+8][kk*8+tig  ]);
            uint32_t a2 = __float_as_uint(p_s[m0+gid  ][kk*8+tig+4]);
            uint32_t a3 = __float_as_uint(p_s[m0+gid+8][kk*8+tig+4]);
            #pragma unroll
            for (int ni = 0; ni < 4; ni++) {
                uint32_t b0 = __float_as_uint(v_s[kk*8+tig  ][ni*8+gid]);
                uint32_t b1 = __float_as_uint(v_s[kk*8+tig+4][ni*8+gid]);
                mma_tf32(o[ni][0], o[ni][1], o[ni][2], o[ni][3], a0, a1, a2, a3, b0, b1);
            }
        }
        __syncwarp();
    }

    // ---- epilogue: duplicate each eff-dim into output pair ----
    const float inv0 = 1.f / lrow0;
    const float inv1 = 1.f / lrow1;
    #pragma unroll
    for (int ni = 0; ni < 4; ni++) {
        const int od = h * HDIM + ni*16 + 4*tig;
        float4 w0, w1;
        w0.x = o[ni][0]*inv0; w0.y = w0.x; w0.z = o[ni][1]*inv0; w0.w = w0.z;
        w1.x = o[ni][2]*inv1; w1.y = w1.x; w1.z = o[ni][3]*inv1; w1.w = w1.z;
        *(float4*)(out + (size_t)(b * TT + r0g) * DD + od) = w0;
        *(float4*)(out + (size_t)(b * TT + r1g) * DD + od) = w1;
    }
}

// ---------------- launch ----------------
extern "C" void kernel_launch(void* const* d_in, const int* in_sizes, int n_in,
                              void* d_out, int out_size) {
    const float* x     = (const float*)d_in[0];
    const float* ln1_g = (const float*)d_in[1];
    const float* ln1_b = (const float*)d_in[2];
    const float* Wqkv  = (const float*)d_in[3];
    const float* bqkv  = (const float*)d_in[4];
    const float* Wo    = (const float*)d_in[5];
    const float* bo    = (const float*)d_in[6];
    const float* ln2_g = (const float*)d_in[7];
    const float* ln2_b = (const float*)d_in[8];
    const float* W1    = (const float*)d_in[9];
    const float* b1    = (const float*)d_in[10];
    const float* W2    = (const float*)d_in[11];
    const float* b2    = (const float*)d_in[12];
    float* out = (float*)d_out;

    float *p_ln1, *p_qkv, *p_attn, *p_h, *p_ln2, *p_ff;
    cudaGetSymbolAddress((void**)&p_ln1,  g_ln1);
    cudaGetSymbolAddress((void**)&p_qkv,  g_qkv);
    cudaGetSymbolAddress((void**)&p_attn, g_attn);
    cudaGetSymbolAddress((void**)&p_h,    g_h);
    cudaGetSymbolAddress((void**)&p_ln2,  g_ln2);
    cudaGetSymbolAddress((void**)&p_ff,   g_ff);

    ln_kernel<<<NTOK, 256>>>(x, ln1_g, ln1_b, p_ln1);
    gemm_tc<false, false><<<dim3(QKV_N / 128, NTOK / 128), 256>>>(
        p_ln1, Wqkv, bqkv, nullptr, p_qkv, NTOK, QKV_N, DD);
    attn_mma<<<dim3(TT / 64, BB * HH), 128>>>(p_qkv, p_attn);
    gemm_tc<false, true><<<dim3(DD / 128, NTOK / 128), 256>>>(
        p_attn, Wo, bo, x, p_h, NTOK, DD, DD);
    ln_kernel<<<NTOK, 256>>>(p_h, ln2_g, ln2_b, p_ln2);
    gemm_tc<true, false><<<dim3(FF_N / 128, NTOK / 128), 256>>>(
        p_ln2, W1, b1, nullptr, p_ff, NTOK, FF_N, DD);
    gemm_tc<false, true><<<dim3(DD / 128, NTOK / 128), 256>>>(
        p_ff, W2, b2, x, out, NTOK, DD, FF_N);
}

// round 7
// speedup vs baseline: 4.8868x; 1.4868x over previous
#include <cuda_runtime.h>
#include <cuda_bf16.h>
#include <cstdint>

// Problem constants
#define BB 8
#define TT 1024
#define DD 1024
#define HH 16
#define KVH 8
#define HDIM 64
#define NTOK (BB*TT)            // 8192
#define QKV_N (DD + 2*KVH*HDIM) // 2048
#define FF_N (4*DD)             // 4096

// ---------------- scratch ----------------
__device__ float g_ln1 [NTOK * DD];
__device__ float g_qkv [NTOK * QKV_N];
__device__ float g_attn[NTOK * DD];
__device__ float g_h   [NTOK * DD];
__device__ float g_ln2 [NTOK * DD];
__device__ float g_ff  [NTOK * FF_N];

// ---------------- helpers ----------------
__device__ __forceinline__ void cp16(uint32_t dst, const void* src) {
    asm volatile("cp.async.ca.shared.global [%0], [%1], 16;\n" :: "r"(dst), "l"(src));
}
__device__ __forceinline__ void cp_commit() {
    asm volatile("cp.async.commit_group;\n" ::: "memory");
}
__device__ __forceinline__ void cp_wait0() {
    asm volatile("cp.async.wait_group 0;\n" ::: "memory");
}
__device__ __forceinline__ void mma_tf32(float& d0, float& d1, float& d2, float& d3,
                                         uint32_t a0, uint32_t a1, uint32_t a2, uint32_t a3,
                                         uint32_t b0, uint32_t b1) {
    asm volatile(
        "mma.sync.aligned.m16n8k8.row.col.f32.tf32.tf32.f32 "
        "{%0,%1,%2,%3}, {%4,%5,%6,%7}, {%8,%9}, {%0,%1,%2,%3};\n"
        : "+f"(d0), "+f"(d1), "+f"(d2), "+f"(d3)
        : "r"(a0), "r"(a1), "r"(a2), "r"(a3), "r"(b0), "r"(b1));
}

// ---------------- LayerNorm ----------------
__global__ void ln_kernel(const float* __restrict__ x, const float* __restrict__ g,
                          const float* __restrict__ b, float* __restrict__ y) {
    __shared__ float red[16];
    const int row = blockIdx.x;
    const int tid = threadIdx.x;
    const float4* xr = (const float4*)(x + (size_t)row * DD);
    float4 v = xr[tid];
    float s  = v.x + v.y + v.z + v.w;
    float s2 = v.x*v.x + v.y*v.y + v.z*v.z + v.w*v.w;
    #pragma unroll
    for (int o = 16; o; o >>= 1) {
        s  += __shfl_xor_sync(0xffffffffu, s,  o);
        s2 += __shfl_xor_sync(0xffffffffu, s2, o);
    }
    const int wid = tid >> 5, lane = tid & 31;
    if (lane == 0) { red[wid] = s; red[wid + 8] = s2; }
    __syncthreads();
    float ts = 0.f, ts2 = 0.f;
    #pragma unroll
    for (int i = 0; i < 8; i++) { ts += red[i]; ts2 += red[i + 8]; }
    const float mu  = ts * (1.0f / DD);
    const float var = ts2 * (1.0f / DD) - mu * mu;
    const float rstd = rsqrtf(var + 1e-5f);
    float4 gv = ((const float4*)g)[tid];
    float4 bv = ((const float4*)b)[tid];
    float4 o;
    o.x = (v.x - mu) * rstd * gv.x + bv.x;
    o.y = (v.y - mu) * rstd * gv.y + bv.y;
    o.z = (v.z - mu) * rstd * gv.z + bv.z;
    o.w = (v.w - mu) * rstd * gv.w + bv.w;
    ((float4*)(y + (size_t)row * DD))[tid] = o;
}

// ---------------- GEMM: cp.async 2-stage pipelined tf32 mma ----------------
// As[m][k] stride 20 (a-frag banks 4*gid+tig: conflict-free)
// Bs[k][n] stride 136 (b-frag banks 8*tig+gid: conflict-free)
template<bool RELU, bool RES>
__global__ void __launch_bounds__(256)
gemm_tc(const float* __restrict__ A, const float* __restrict__ B,
        const float* __restrict__ bias, const float* __restrict__ res,
        float* __restrict__ C, int M, int N, int K) {
    __shared__ float As[2][128][20];
    __shared__ float Bs[2][16][136];

    const int tid  = threadIdx.x;
    const int lane = tid & 31;
    const int wid  = tid >> 5;
    const int gid  = lane >> 2;
    const int tig  = lane & 3;
    const int warpM = (wid & 1) * 64;
    const int warpN = (wid >> 1) * 32;

    const int bm = blockIdx.y * 128;
    const int bn = blockIdx.x * 128;

    const int ar = tid >> 2;          // 0..63 (+64)
    const int ac = (tid & 3) * 4;     // 0,4,8,12
    const int br = tid >> 5;          // 0..7 (+8)
    const int bc = (tid & 31) * 4;    // 0..124

    const uint32_t as_base = (uint32_t)__cvta_generic_to_shared(&As[0][0][0]);
    const uint32_t bs_base = (uint32_t)__cvta_generic_to_shared(&Bs[0][0][0]);

    float c[4][4][4];
    #pragma unroll
    for (int i = 0; i < 4; i++)
        #pragma unroll
        for (int j = 0; j < 4; j++)
            #pragma unroll
            for (int q = 0; q < 4; q++) c[i][j][q] = 0.f;

    auto issue_stage = [&](int buf, int k0) {
        #pragma unroll
        for (int i = 0; i < 2; i++) {
            uint32_t dst = as_base + (((buf * 128 + ar + i * 64) * 20 + ac) << 2);
            cp16(dst, A + (size_t)(bm + ar + i * 64) * K + k0 + ac);
        }
        #pragma unroll
        for (int i = 0; i < 2; i++) {
            uint32_t dst = bs_base + (((buf * 16 + br + i * 8) * 136 + bc) << 2);
            cp16(dst, B + (size_t)(k0 + br + i * 8) * N + bn + bc);
        }
        cp_commit();
    };

    issue_stage(0, 0);
    const int nT = K / 16;
    for (int t = 0; t < nT; t++) {
        cp_wait0();
        __syncthreads();
        if (t + 1 < nT) issue_stage((t + 1) & 1, (t + 1) * 16);
        const int cur = t & 1;
        #pragma unroll
        for (int kk = 0; kk < 16; kk += 8) {
            uint32_t af[4][4], bf[4][2];
            #pragma unroll
            for (int mi = 0; mi < 4; mi++) {
                const int m0 = warpM + mi * 16 + gid;
                af[mi][0] = __float_as_uint(As[cur][m0    ][kk + tig    ]);
                af[mi][1] = __float_as_uint(As[cur][m0 + 8][kk + tig    ]);
                af[mi][2] = __float_as_uint(As[cur][m0    ][kk + tig + 4]);
                af[mi][3] = __float_as_uint(As[cur][m0 + 8][kk + tig + 4]);
            }
            #pragma unroll
            for (int ni = 0; ni < 4; ni++) {
                const int n0 = warpN + ni * 8 + gid;
                bf[ni][0] = __float_as_uint(Bs[cur][kk + tig    ][n0]);
                bf[ni][1] = __float_as_uint(Bs[cur][kk + tig + 4][n0]);
            }
            #pragma unroll
            for (int mi = 0; mi < 4; mi++)
                #pragma unroll
                for (int ni = 0; ni < 4; ni++)
                    mma_tf32(c[mi][ni][0], c[mi][ni][1], c[mi][ni][2], c[mi][ni][3],
                             af[mi][0], af[mi][1], af[mi][2], af[mi][3],
                             bf[ni][0], bf[ni][1]);
        }
    }

    #pragma unroll
    for (int mi = 0; mi < 4; mi++) {
        #pragma unroll
        for (int ni = 0; ni < 4; ni++) {
            const int col = bn + warpN + ni * 8 + 2 * tig;
            const size_t r0 = (size_t)(bm + warpM + mi * 16 + gid);
            const size_t r1 = r0 + 8;
            float2 bi = *(const float2*)(bias + col);
            float2 o0, o1;
            o0.x = c[mi][ni][0] + bi.x; o0.y = c[mi][ni][1] + bi.y;
            o1.x = c[mi][ni][2] + bi.x; o1.y = c[mi][ni][3] + bi.y;
            if (RES) {
                float2 v0 = *(const float2*)(res + r0 * N + col);
                float2 v1 = *(const float2*)(res + r1 * N + col);
                o0.x += v0.x; o0.y += v0.y; o1.x += v1.x; o1.y += v1.y;
            }
            if (RELU) {
                o0.x = fmaxf(o0.x, 0.f); o0.y = fmaxf(o0.y, 0.f);
                o1.x = fmaxf(o1.x, 0.f); o1.y = fmaxf(o1.y, 0.f);
            }
            *(float2*)(C + r0 * N + col) = o0;
            *(float2*)(C + r1 * N + col) = o1;
        }
    }
}

// ---------------- Attention: tf32 mma + cp.async double-buffered K/V ----------------
// Effective GQA (elementwise jnp.repeat): head h uses 32-dim slices
//   k_eff[j]=kraw[h*32+j], q_eff[j]=q[h*64+2j]+q[h*64+2j+1], out duplicated in pairs.
__global__ void __launch_bounds__(128)
attn_mma(const float* __restrict__ qkv, float* __restrict__ out) {
    __shared__ float q_s[64][36];
    __shared__ float k_s[2][32][36];
    __shared__ float v_s[2][32][40];
    __shared__ float p_s[64][36];

    const int tid  = threadIdx.x;
    const int lane = tid & 31;
    const int warp = tid >> 5;
    const int gid  = lane >> 2;   // 0..7
    const int tig  = lane & 3;    // 0..3
    const int b   = blockIdx.y >> 4;
    const int h   = blockIdx.y & 15;
    const int qt0 = blockIdx.x * 64;
    const float* base = qkv + (size_t)b * TT * QKV_N;

    const uint32_t ks_base = (uint32_t)__cvta_generic_to_shared(&k_s[0][0][0]);
    const uint32_t vs_base = (uint32_t)__cvta_generic_to_shared(&v_s[0][0][0]);

    // q_eff tile 64x32, raw fp32 (tf32 mma truncates)
    {
        const int row = tid >> 1, half = tid & 1;
        const float4* qr = (const float4*)(base + (size_t)(qt0 + row) * QKV_N + h * HDIM + half * 32);
        #pragma unroll
        for (int i = 0; i < 8; i++) {
            float4 v = qr[i];
            q_s[row][half*16 + 2*i]     = v.x + v.y;
            q_s[row][half*16 + 2*i + 1] = v.z + v.w;
        }
    }

    // cp.async K/V tile loader: 32 rows x 32 floats each
    const int kvr = tid >> 2;            // 0..31
    const int kvc = (tid & 3) * 8;       // 0,8,16,24
    auto issue_kv = [&](int buf, int s) {
        const float* kr = base + (size_t)(s + kvr) * QKV_N + DD + h * 32 + kvc;
        uint32_t kd = ks_base + (((buf * 32 + kvr) * 36 + kvc) << 2);
        uint32_t vd = vs_base + (((buf * 32 + kvr) * 40 + kvc) << 2);
        cp16(kd,      kr);
        cp16(kd + 16, kr + 4);
        cp16(vd,      kr + KVH * HDIM);
        cp16(vd + 16, kr + KVH * HDIM + 4);
        cp_commit();
    };

    const int m0 = warp * 16;
    const int r0g = qt0 + m0 + gid;
    const int r1g = r0g + 8;
    float mrow0 = -1e30f, mrow1 = -1e30f, lrow0 = 0.f, lrow1 = 0.f;
    float o[4][4];
    #pragma unroll
    for (int i = 0; i < 4; i++)
        #pragma unroll
        for (int j = 0; j < 4; j++) o[i][j] = 0.f;

    issue_kv(0, 0);
    const int nTiles = (qt0 + 64) / 32;
    for (int ti = 0; ti < nTiles; ti++) {
        cp_wait0();
        __syncthreads();   // K/V visible block-wide; also covers q_s (first iter) and
                           // guarantees compute(ti-1) done before buf (ti+1)&1 overwrite
        if (ti + 1 < nTiles) issue_kv((ti + 1) & 1, (ti + 1) * 32);
        const int cur = ti & 1;
        const int s = ti * 32;

        // ---- S = Q K^T : 16x32 per warp ----
        float c[4][4];
        #pragma unroll
        for (int ni = 0; ni < 4; ni++)
            #pragma unroll
            for (int q = 0; q < 4; q++) c[ni][q] = 0.f;

        #pragma unroll
        for (int kk = 0; kk < 4; kk++) {
            uint32_t a0 = __float_as_uint(q_s[m0+gid  ][kk*8+tig  ]);
            uint32_t a1 = __float_as_uint(q_s[m0+gid+8][kk*8+tig  ]);
            uint32_t a2 = __float_as_uint(q_s[m0+gid  ][kk*8+tig+4]);
            uint32_t a3 = __float_as_uint(q_s[m0+gid+8][kk*8+tig+4]);
            #pragma unroll
            for (int ni = 0; ni < 4; ni++) {
                uint32_t b0 = __float_as_uint(k_s[cur][ni*8+gid][kk*8+tig  ]);
                uint32_t b1 = __float_as_uint(k_s[cur][ni*8+gid][kk*8+tig+4]);
                mma_tf32(c[ni][0], c[ni][1], c[ni][2], c[ni][3], a0, a1, a2, a3, b0, b1);
            }
        }

        // ---- scale + causal mask ----
        #pragma unroll
        for (int ni = 0; ni < 4; ni++) {
            const int col = s + ni*8 + 2*tig;
            c[ni][0] = (col   <= r0g) ? c[ni][0]*0.125f : -1e30f;
            c[ni][1] = (col+1 <= r0g) ? c[ni][1]*0.125f : -1e30f;
            c[ni][2] = (col   <= r1g) ? c[ni][2]*0.125f : -1e30f;
            c[ni][3] = (col+1 <= r1g) ? c[ni][3]*0.125f : -1e30f;
        }

        // ---- row max + quad reduce ----
        float mt0 = c[0][0], mt1 = c[0][2];
        #pragma unroll
        for (int ni = 0; ni < 4; ni++) {
            mt0 = fmaxf(mt0, fmaxf(c[ni][0], c[ni][1]));
            mt1 = fmaxf(mt1, fmaxf(c[ni][2], c[ni][3]));
        }
        #pragma unroll
        for (int off = 1; off <= 2; off <<= 1) {
            mt0 = fmaxf(mt0, __shfl_xor_sync(0xffffffffu, mt0, off));
            mt1 = fmaxf(mt1, __shfl_xor_sync(0xffffffffu, mt1, off));
        }
        const float mn0 = fmaxf(mrow0, mt0);
        const float mn1 = fmaxf(mrow1, mt1);
        const float al0 = __expf(mrow0 - mn0);
        const float al1 = __expf(mrow1 - mn1);
        mrow0 = mn0; mrow1 = mn1;

        // ---- p = exp(s-m), partial sums, store raw fp32 to p_s ----
        float ps0 = 0.f, ps1 = 0.f;
        #pragma unroll
        for (int ni = 0; ni < 4; ni++) {
            float p00 = __expf(c[ni][0] - mn0);
            float p01 = __expf(c[ni][1] - mn0);
            float p10 = __expf(c[ni][2] - mn1);
            float p11 = __expf(c[ni][3] - mn1);
            ps0 += p00 + p01; ps1 += p10 + p11;
            float2 w0; w0.x = p00; w0.y = p01;
            float2 w1; w1.x = p10; w1.y = p11;
            *(float2*)&p_s[m0+gid  ][ni*8 + 2*tig] = w0;
            *(float2*)&p_s[m0+gid+8][ni*8 + 2*tig] = w1;
        }
        #pragma unroll
        for (int off = 1; off <= 2; off <<= 1) {
            ps0 += __shfl_xor_sync(0xffffffffu, ps0, off);
            ps1 += __shfl_xor_sync(0xffffffffu, ps1, off);
        }
        lrow0 = lrow0 * al0 + ps0;
        lrow1 = lrow1 * al1 + ps1;
        #pragma unroll
        for (int ni = 0; ni < 4; ni++) {
            o[ni][0] *= al0; o[ni][1] *= al0;
            o[ni][2] *= al1; o[ni][3] *= al1;
        }
        __syncwarp();   // order p_s STS before LDS (warp-private rows)

        // ---- O += P V : 16x32 per warp ----
        #pragma unroll
        for (int kk = 0; kk < 4; kk++) {
            uint32_t a0 = __float_as_uint(p_s[m0+gid  ][kk*8+tig  ]);
            uint32_t a1 = __float_as_uint(p_s[m0+gid+8][kk*8+tig  ]);
            uint32_t a2 = __float_as_uint(p_s[m0+gid  ][kk*8+tig+4]);
            uint32_t a3 = __float_as_uint(p_s[m0+gid+8][kk*8+tig+4]);
            #pragma unroll
            for (int ni = 0; ni < 4; ni++) {
                uint32_t b0 = __float_as_uint(v_s[cur][kk*8+tig  ][ni*8+gid]);
                uint32_t b1 = __float_as_uint(v_s[cur][kk*8+tig+4][ni*8+gid]);
                mma_tf32(o[ni][0], o[ni][1], o[ni][2], o[ni][3], a0, a1, a2, a3, b0, b1);
            }
        }
        __syncwarp();
    }

    // ---- epilogue: duplicate each eff-dim into output pair ----
    const float inv0 = 1.f / lrow0;
    const float inv1 = 1.f / lrow1;
    #pragma unroll
    for (int ni = 0; ni < 4; ni++) {
        const int od = h * HDIM + ni*16 + 4*tig;
        float4 w0, w1;
        w0.x = o[ni][0]*inv0; w0.y = w0.x; w0.z = o[ni][1]*inv0; w0.w = w0.z;
        w1.x = o[ni][2]*inv1; w1.y = w1.x; w1.z = o[ni][3]*inv1; w1.w = w1.z;
        *(float4*)(out + (size_t)(b * TT + r0g) * DD + od) = w0;
        *(float4*)(out + (size_t)(b * TT + r1g) * DD + od) = w1;
    }
}

// ---------------- launch ----------------
extern "C" void kernel_launch(void* const* d_in, const int* in_sizes, int n_in,
                              void* d_out, int out_size) {
    const float* x     = (const float*)d_in[0];
    const float* ln1_g = (const float*)d_in[1];
    const float* ln1_b = (const float*)d_in[2];
    const float* Wqkv  = (const float*)d_in[3];
    const float* bqkv  = (const float*)d_in[4];
    const float* Wo    = (const float*)d_in[5];
    const float* bo    = (const float*)d_in[6];
    const float* ln2_g = (const float*)d_in[7];
    const float* ln2_b = (const float*)d_in[8];
    const float* W1    = (const float*)d_in[9];
    const float* b1    = (const float*)d_in[10];
    const float* W2    = (const float*)d_in[11];
    const float* b2    = (const float*)d_in[12];
    float* out = (float*)d_out;

    float *p_ln1, *p_qkv, *p_attn, *p_h, *p_ln2, *p_ff;
    cudaGetSymbolAddress((void**)&p_ln1,  g_ln1);
    cudaGetSymbolAddress((void**)&p_qkv,  g_qkv);
    cudaGetSymbolAddress((void**)&p_attn, g_attn);
    cudaGetSymbolAddress((void**)&p_h,    g_h);
    cudaGetSymbolAddress((void**)&p_ln2,  g_ln2);
    cudaGetSymbolAddress((void**)&p_ff,   g_ff);

    ln_kernel<<<NTOK, 256>>>(x, ln1_g, ln1_b, p_ln1);
    gemm_tc<false, false><<<dim3(QKV_N / 128, NTOK / 128), 256>>>(
        p_ln1, Wqkv, bqkv, nullptr, p_qkv, NTOK, QKV_N, DD);
    attn_mma<<<dim3(TT / 64, BB * HH), 128>>>(p_qkv, p_attn);
    gemm_tc<false, true><<<dim3(DD / 128, NTOK / 128), 256>>>(
        p_attn, Wo, bo, x, p_h, NTOK, DD, DD);
    ln_kernel<<<NTOK, 256>>>(p_h, ln2_g, ln2_b, p_ln2);
    gemm_tc<true, false><<<dim3(FF_N / 128, NTOK / 128), 256>>>(
        p_ln2, W1, b1, nullptr, p_ff, NTOK, FF_N, DD);
    gemm_tc<false, true><<<dim3(DD / 128, NTOK / 128), 256>>>(
        p_ff, W2, b2, x, out, NTOK, DD, FF_N);
}